// round 14
// baseline (speedup 1.0000x reference)
#include <cuda_runtime.h>
#include <math.h>
#include <stdint.h>

#define D      768
#define SLEN   2048
#define BATCH  32
#define CHUNKS 16
#define TILE   32
#define NTILE  4
#define NTHR   256

// ---------------- scratch ----------------
__device__ float g_scratch[1500000];
#define OFF_PA       0        // 32*768
#define OFF_U        24576    // 32*768
#define OFF_LOGITS   49152    // 32*2048
#define OFF_MPART    114688   // 32*16*3 = 1536
#define OFF_LPART    116224   // 1536
#define OFF_ACCPART  117760   // 32*16*3*768 = 1179648
#define OFF_XFUSE    1297408  // 64*1536 = 98304
#define OFF_LIN      1395712  // 128*768 = 98304 (pa_lin | cq_lin | fuse_lin) -> total 1494016

// ---------------- f32x2 helpers ----------------
__device__ __forceinline__ unsigned long long pack2(float lo, float hi) {
    unsigned long long r;
    asm("mov.b64 %0,{%1,%2};" : "=l"(r) : "f"(lo), "f"(hi));
    return r;
}
__device__ __forceinline__ void unpack2(unsigned long long v, float& lo, float& hi) {
    asm("mov.b64 {%0,%1},%2;" : "=f"(lo), "=f"(hi) : "l"(v));
}
__device__ __forceinline__ void fma2(unsigned long long& d, unsigned long long a,
                                     unsigned long long b) {
    asm("fma.rn.f32x2 %0,%1,%2,%0;" : "+l"(d) : "l"(a), "l"(b));
}
__device__ __forceinline__ void mul2(unsigned long long& d, unsigned long long a) {
    asm("mul.rn.f32x2 %0,%0,%1;" : "+l"(d) : "l"(a));
}

// ---------------- reductions ----------------
__device__ __forceinline__ float block_sum256(float v, float* red) {
    int lane = threadIdx.x & 31, w = threadIdx.x >> 5;
#pragma unroll
    for (int o = 16; o; o >>= 1) v += __shfl_down_sync(0xffffffffu, v, o);
    if (lane == 0) red[w] = v;
    __syncthreads();
    if (w == 0) {
        float x = (lane < 8) ? red[lane] : 0.f;
#pragma unroll
        for (int o = 4; o; o >>= 1) x += __shfl_down_sync(0xffffffffu, x, o);
        if (lane == 0) red[0] = x;
    }
    __syncthreads();
    float r = red[0];
    __syncthreads();
    return r;
}

__device__ __forceinline__ float block_sum768(float v, float* red) {
    int lane = threadIdx.x & 31, w = threadIdx.x >> 5;
#pragma unroll
    for (int o = 16; o; o >>= 1) v += __shfl_down_sync(0xffffffffu, v, o);
    if (lane == 0) red[w] = v;
    __syncthreads();
    if (w == 0) {
        float x = (lane < 24) ? red[lane] : 0.f;
#pragma unroll
        for (int o = 16; o; o >>= 1) x += __shfl_down_sync(0xffffffffu, x, o);
        if (lane == 0) red[0] = x;
    }
    __syncthreads();
    float r = red[0];
    __syncthreads();
    return r;
}

// ---------------- zero the lin accumulation buffers ----------------
__global__ void k_zero(float* __restrict__ p, int n4) {
    int i = blockIdx.x * 256 + threadIdx.x;
    if (i < n4) ((float4*)p)[i] = make_float4(0.f, 0.f, 0.f, 0.f);
}

// ---------------- weight-streaming split-K GEMM (f32x2) -> atomic accumulate into lin ------
template <int KS, int RACC>
__global__ void k_gemm2(const float* __restrict__ X1, int K1, int s1,
                        const float* __restrict__ X2, int s2,
                        const float* __restrict__ W, int K,
                        float* __restrict__ lin, const int* __restrict__ step_sel) {
    __shared__ __align__(16) float xs[KS * RACC];  // transposed: [kk][r]
    int tid = threadIdx.x;
    int j = blockIdx.x * 256 + tid;
    int k0 = blockIdx.y * KS;
    int r0 = blockIdx.z * RACC;

    const float* Wb = W;
    if (step_sel) Wb += (size_t)(*step_sel) * K * D;

    for (int i = tid; i < KS * RACC; i += 256) {
        int r = i / KS, kk = i - r * KS;
        int k = k0 + kk;
        float v = (k < K1) ? X1[(size_t)(r0 + r) * s1 + k]
                           : X2[(size_t)(r0 + r) * s2 + (k - K1)];
        xs[kk * RACC + r] = v;
    }
    __syncthreads();

    unsigned long long acc2[RACC / 2];
#pragma unroll
    for (int p = 0; p < RACC / 2; p++) acc2[p] = 0ull;

    // UNR must divide KS exactly (OOB otherwise)
    constexpr int UNR = (KS % 16 == 0) ? 16 : 8;
    static_assert(KS % UNR == 0, "UNR must divide KS");
    for (int kk0 = 0; kk0 < KS; kk0 += UNR) {
        float w[UNR];
#pragma unroll
        for (int u = 0; u < UNR; u++) w[u] = Wb[(size_t)(k0 + kk0 + u) * D + j];
#pragma unroll
        for (int u = 0; u < UNR; u++) {
            unsigned long long w2 = pack2(w[u], w[u]);
            const float4* xr = (const float4*)(xs + (kk0 + u) * RACC);
#pragma unroll
            for (int p = 0; p < RACC / 4; p++) {
                float4 xv = xr[p];
                fma2(acc2[2 * p], pack2(xv.x, xv.y), w2);
                fma2(acc2[2 * p + 1], pack2(xv.z, xv.w), w2);
            }
        }
    }

    float* dst = lin + (size_t)r0 * D + j;
#pragma unroll
    for (int p = 0; p < RACC / 2; p++) {
        float lo, hi;
        unpack2(acc2[p], lo, hi);
        atomicAdd(&dst[(size_t)(2 * p) * D], lo);
        atomicAdd(&dst[(size_t)(2 * p + 1) * D], hi);
    }
}

// ---------------- bias + LN + ReLU (+mul / fuse split-write) on lin rows ----------------
__global__ void k_reduce_ln(const float* __restrict__ lin,
                            const float* __restrict__ bias, const int* __restrict__ step_sel,
                            float* __restrict__ out,
                            const float* __restrict__ g1, const float* __restrict__ b1,
                            const float* __restrict__ g2, const float* __restrict__ b2,
                            const float* __restrict__ wmul, int fuse_map) {
    __shared__ float red[32];
    int r = blockIdx.x, tid = threadIdx.x;
    const float* bb = bias;
    if (step_sel) bb += (size_t)(*step_sel) * D;

    float a = lin[(size_t)r * D + tid] + bb[tid];

    float su = block_sum768(a, red);
    float mu = su * (1.f / D);
    float dd = a - mu;
    float ss = block_sum768(dd * dd, red);
    float inv = rsqrtf(ss * (1.f / D) + 1e-5f);

    const float* g = g1;
    const float* bv = b1;
    float* dst;
    if (fuse_map) {
        int half = r >> 5, bidx = r & 31;
        dst = out + (size_t)bidx * 1536 + half * 768;
        if (half) { g = g2; bv = b2; }
    } else {
        dst = out + (size_t)r * D;
    }
    float y = fmaxf(dd * inv * g[tid] + bv[tid], 0.f);
    if (wmul) y *= wmul[tid];
    dst[tid] = y;
}

// ---------------- main pass: 32-row tiles, cp.async staging, 2 CTAs/SM, all-SM grid ----------
// grid (32, 16) = 512 CTAs (1.73 waves at 2/SM -> all 148 SMs busy), 4 tiles of 32 rows.
__global__ void k_main(const float* __restrict__ ctx, const float* __restrict__ qm1,
                       const float* __restrict__ qm2, const float* __restrict__ battn,
                       const float* __restrict__ u, float* __restrict__ logits,
                       float* __restrict__ mpart, float* __restrict__ lpart,
                       float* __restrict__ accpart) {
    extern __shared__ __align__(16) float sm[];
    float* ctx_sh   = sm;          // 24576
    float* dot_sh   = sm + 24576;  // 32
    float* pa_sh    = sm + 24608;  // 96
    float* q1_sh    = sm + 24704;  // 32
    float* q2_sh    = sm + 24736;  // 32
    float* scale_sh = sm + 24768;  // 4

    int b = blockIdx.x, ch = blockIdx.y;
    int tid = threadIdx.x;
    int w = tid >> 5, lane = tid & 31;

    float u_reg[24];
    {
        const float* ub = u + (size_t)b * D;
#pragma unroll
        for (int i = 0; i < 24; i++) u_reg[i] = ub[lane + 32 * i];
    }

    unsigned long long acc2[3][2];
#pragma unroll
    for (int t3 = 0; t3 < 3; t3++) { acc2[t3][0] = 0ull; acc2[t3][1] = 0ull; }

    float m_r = -INFINITY, l_r = 0.f;
    const float ba = battn[0];
    const float SC = 0.03608439182435161f;  // 1/sqrt(768)

    uint32_t ctx_sa = (uint32_t)__cvta_generic_to_shared(ctx_sh);
    uint32_t q1_sa  = (uint32_t)__cvta_generic_to_shared(q1_sh);
    uint32_t q2_sa  = (uint32_t)__cvta_generic_to_shared(q2_sh);

    for (int t = 0; t < NTILE; t++) {
        int sbase = ch * (NTILE * TILE) + t * TILE;
        const float4* src = (const float4*)(ctx + ((size_t)b * SLEN + sbase) * D);
#pragma unroll
        for (int i = 0; i < 24; i++) {
            int idx = tid + NTHR * i;
            asm volatile("cp.async.cg.shared.global [%0],[%1],16;"
                         :: "r"(ctx_sa + idx * 16), "l"(src + idx));
        }
        if (tid < 32) {
            asm volatile("cp.async.ca.shared.global [%0],[%1],4;"
                         :: "r"(q1_sa + tid * 4), "l"(qm1 + (size_t)b * SLEN + sbase + tid));
        } else if (tid < 64) {
            asm volatile("cp.async.ca.shared.global [%0],[%1],4;"
                         :: "r"(q2_sa + (tid - 32) * 4),
                            "l"(qm2 + (size_t)b * SLEN + sbase + (tid - 32)));
        }
        asm volatile("cp.async.commit_group;");
        asm volatile("cp.async.wait_group 0;");
        __syncthreads();

        // dots: warp w handles s = 4w..4w+3
#pragma unroll
        for (int q = 0; q < 4; q++) {
            int s = w * 4 + q;
            const float* cp = ctx_sh + s * D;
            float a0 = 0.f, a1 = 0.f;
#pragma unroll
            for (int i = 0; i < 24; i += 2) {
                a0 = fmaf(cp[lane + 32 * i], u_reg[i], a0);
                a1 = fmaf(cp[lane + 32 * (i + 1)], u_reg[i + 1], a1);
            }
            float a = a0 + a1;
#pragma unroll
            for (int o = 16; o; o >>= 1) a += __shfl_down_sync(0xffffffffu, a, o);
            if (lane == 0) dot_sh[s] = a;
        }
        __syncthreads();

        // softmax bookkeeping: warps 0-2 handle mask types; warp 3 writes logits
        if (w < 3) {
            float L = (dot_sh[lane] + ba) * SC;
            float q1 = q1_sh[lane], q2 = q2_sh[lane];
            float qv = (w == 0) ? (q1 + q2) : ((w == 1) ? q1 : q2);
            float lg = (qv > 0.f) ? L : -1e9f;
            float msk = (w == 0) ? 1.f : ((qv > 0.f) ? 1.f : 0.f);
            float mx = lg;
#pragma unroll
            for (int o = 16; o; o >>= 1) mx = fmaxf(mx, __shfl_xor_sync(0xffffffffu, mx, o));
            float mnew = fmaxf(m_r, mx);
            float p = expf(lg - mnew);
            float psv = p;
#pragma unroll
            for (int o = 16; o; o >>= 1) psv += __shfl_xor_sync(0xffffffffu, psv, o);
            float sc = expf(m_r - mnew);
            l_r = l_r * sc + psv;
            m_r = mnew;
            pa_sh[w * 32 + lane] = p * msk;
            if (lane == 0) scale_sh[w] = sc;
        } else if (w == 3) {
            logits[(size_t)b * SLEN + sbase + lane] = (dot_sh[lane] + ba) * SC;
        }
        __syncthreads();

        // accumulate: 192 threads x 4 consecutive cols, f32x2 FMAs
        if (tid < 192) {
            unsigned long long s20 = pack2(scale_sh[0], scale_sh[0]);
            unsigned long long s21 = pack2(scale_sh[1], scale_sh[1]);
            unsigned long long s22 = pack2(scale_sh[2], scale_sh[2]);
            mul2(acc2[0][0], s20); mul2(acc2[0][1], s20);
            mul2(acc2[1][0], s21); mul2(acc2[1][1], s21);
            mul2(acc2[2][0], s22); mul2(acc2[2][1], s22);
            const float4* cb = (const float4*)ctx_sh + tid;
#pragma unroll 4
            for (int s = 0; s < TILE; s++) {
                float4 c = cb[s * (D / 4)];
                unsigned long long c01 = pack2(c.x, c.y);
                unsigned long long c23 = pack2(c.z, c.w);
                unsigned long long p0 = pack2(pa_sh[s], pa_sh[s]);
                unsigned long long p1 = pack2(pa_sh[32 + s], pa_sh[32 + s]);
                unsigned long long p2 = pack2(pa_sh[64 + s], pa_sh[64 + s]);
                fma2(acc2[0][0], c01, p0); fma2(acc2[0][1], c23, p0);
                fma2(acc2[1][0], c01, p1); fma2(acc2[1][1], c23, p1);
                fma2(acc2[2][0], c01, p2); fma2(acc2[2][1], c23, p2);
            }
        }
        __syncthreads();  // ctx_sh reused by next tile's cp.async
    }

    if (tid < 192) {
#pragma unroll
        for (int t3 = 0; t3 < 3; t3++) {
            float4 o;
            unpack2(acc2[t3][0], o.x, o.y);
            unpack2(acc2[t3][1], o.z, o.w);
            ((float4*)(accpart + ((size_t)(b * CHUNKS + ch) * 3 + t3) * D))[tid] = o;
        }
    }
    if (w < 3 && lane == 0) {
        mpart[(b * CHUNKS + ch) * 3 + w] = m_r;
        lpart[(b * CHUNKS + ch) * 3 + w] = l_r;
    }
}

// ---------------- combine partials + l2norm + xfuse + attention maps ----------------
__global__ void k_combine_attn(const float* __restrict__ mpart, const float* __restrict__ lpart,
                               const float* __restrict__ accpart,
                               const float* __restrict__ logits,
                               const float* __restrict__ qm1, const float* __restrict__ qm2,
                               float* __restrict__ xfuse, float* __restrict__ attn_out) {
    __shared__ float red[32];
    int b = blockIdx.x, t = blockIdx.y, tid = threadIdx.x;
    float m = -INFINITY;
#pragma unroll
    for (int c = 0; c < CHUNKS; c++) m = fmaxf(m, mpart[(b * CHUNKS + c) * 3 + t]);
    float l = 0.f;
    float v[3] = {0.f, 0.f, 0.f};
#pragma unroll
    for (int c = 0; c < CHUNKS; c++) {
        float wgt = expf(mpart[(b * CHUNKS + c) * 3 + t] - m);
        l += lpart[(b * CHUNKS + c) * 3 + t] * wgt;
        const float* ap = accpart + ((size_t)(b * CHUNKS + c) * 3 + t) * D;
#pragma unroll
        for (int i = 0; i < 3; i++) v[i] = fmaf(ap[tid + 256 * i], wgt, v[i]);
    }
#pragma unroll
    for (int i = 0; i < 3; i++) v[i] /= l;
    float ss = block_sum256(v[0] * v[0] + v[1] * v[1] + v[2] * v[2], red);
    float inv = 1.f / fmaxf(sqrtf(ss), 1e-12f);
#pragma unroll
    for (int i = 0; i < 3; i++) v[i] *= inv;

    if (t == 0) {
        float* d1 = xfuse + (size_t)b * 1536 + 768;
        float* d2 = xfuse + (size_t)(BATCH + b) * 1536 + 768;
#pragma unroll
        for (int i = 0; i < 3; i++) {
            d1[tid + 256 * i] = v[i];
            d2[tid + 256 * i] = v[i];
        }
    } else {
        float* d1 = (t == 1) ? (xfuse + (size_t)b * 1536) : (xfuse + (size_t)(BATCH + b) * 1536);
#pragma unroll
        for (int i = 0; i < 3; i++) d1[tid + 256 * i] = v[i];
    }

    // attention row for (b, t)
    float invl = 1.f / l;
    float* dst = attn_out + ((size_t)b * 3 + t) * SLEN;
#pragma unroll
    for (int i = 0; i < SLEN / 256; i++) {
        int s = tid + 256 * i;
        size_t idx = (size_t)b * SLEN + s;
        float L = logits[idx];
        float qv = (t == 0) ? (qm1[idx] + qm2[idx]) : ((t == 1) ? qm1[idx] : qm2[idx]);
        float lg = (qv > 0.f) ? L : -1e9f;
        dst[s] = expf(lg - m) * invl;
    }
}

// ---------------- launch ----------------
extern "C" void kernel_launch(void* const* d_in, const int* in_sizes, int n_in,
                              void* d_out, int out_size) {
    const int*   step     = (const int*)d_in[0];
    const float* ctx      = (const float*)d_in[1];
    const float* question = (const float*)d_in[2];
    const float* control  = (const float*)d_in[3];
    const float* qm1      = (const float*)d_in[4];
    const float* qm2      = (const float*)d_in[5];
    const float* W_pos    = (const float*)d_in[8];
    const float* b_pos    = (const float*)d_in[9];
    const float* ln1_g    = (const float*)d_in[10];
    const float* ln1_b    = (const float*)d_in[11];
    const float* W_cq     = (const float*)d_in[12];
    const float* b_cq     = (const float*)d_in[13];
    const float* ln2_g    = (const float*)d_in[14];
    const float* ln2_b    = (const float*)d_in[15];
    const float* W_attn   = (const float*)d_in[16];
    const float* b_attn   = (const float*)d_in[17];
    const float* W_fuse   = (const float*)d_in[18];
    const float* b_fuse   = (const float*)d_in[19];
    const float* ln3_g    = (const float*)d_in[20];
    const float* ln3_b    = (const float*)d_in[21];
    const float* ln4_g    = (const float*)d_in[22];
    const float* ln4_b    = (const float*)d_in[23];
    float* out = (float*)d_out;

    void* sp = nullptr;
    cudaGetSymbolAddress(&sp, g_scratch);
    float* s = (float*)sp;
    float* lin_pa   = s + OFF_LIN;           // 32*768
    float* lin_cq   = s + OFF_LIN + 24576;   // 32*768
    float* lin_fuse = s + OFF_LIN + 49152;   // 64*768

    const int mainSmem = 24772 * 4;  // ~99KB -> 2 CTAs/SM
    cudaFuncSetAttribute(k_main, cudaFuncAttributeMaxDynamicSharedMemorySize, mainSmem);

    // zero all three lin accumulation buffers (128*768 floats = 24576 float4s)
    k_zero<<<96, 256>>>(s + OFF_LIN, 24576);

    // pa = ln_relu(question @ W_pos[step] + b_pos[step])  (96 slices, 1152 CTAs, atomic acc)
    k_gemm2<8, 8><<<dim3(3, 96, 4), NTHR>>>(question, 768, 768, nullptr, 0, W_pos, 768,
                                            lin_pa, step);
    k_reduce_ln<<<32, 768>>>(lin_pa, b_pos, step, s + OFF_PA,
                             ln1_g, ln1_b, nullptr, nullptr, nullptr, 0);
    // u = ln_relu([control|pa] @ W_cq + b_cq) * W_attn    (96 slices, 1152 CTAs, atomic acc)
    k_gemm2<24, 8><<<dim3(3, 96, 4), NTHR>>>(control, 1536, 1536, s + OFF_PA, 768, W_cq, 2304,
                                             lin_cq, nullptr);
    k_reduce_ln<<<32, 768>>>(lin_cq, b_cq, nullptr, s + OFF_U,
                             ln2_g, ln2_b, nullptr, nullptr, W_attn, 0);
    // main context pass (512 CTAs, all SMs, cp.async staging)
    k_main<<<dim3(BATCH, CHUNKS), NTHR, mainSmem>>>(ctx, qm1, qm2, b_attn, s + OFF_U,
                                                    s + OFF_LOGITS, s + OFF_MPART,
                                                    s + OFF_LPART, s + OFF_ACCPART);
    // combine + l2norm + xfuse + attention maps
    k_combine_attn<<<dim3(BATCH, 3), NTHR>>>(s + OFF_MPART, s + OFF_LPART, s + OFF_ACCPART,
                                             s + OFF_LOGITS, qm1, qm2, s + OFF_XFUSE,
                                             out + BATCH * 1536);
    // ctrl1/ctrl2 = ln_relu(xfuse @ W_fuse + b_fuse) -> out (96 slices, 2304 CTAs, atomic acc)
    k_gemm2<16, 8><<<dim3(3, 96, 8), NTHR>>>(s + OFF_XFUSE, 1536, 1536, nullptr, 0, W_fuse,
                                             1536, lin_fuse, nullptr);
    k_reduce_ln<<<64, 768>>>(lin_fuse, b_fuse, nullptr, out,
                             ln3_g, ln3_b, ln4_g, ln4_b, nullptr, 1);
}

// round 15
// speedup vs baseline: 1.0188x; 1.0188x over previous
#include <cuda_runtime.h>
#include <math.h>
#include <stdint.h>

#define D      768
#define SLEN   2048
#define BATCH  32
#define CHUNKS 16
#define TILE   32
#define NTILE  4
#define NTHR   256

// ---------------- scratch ----------------
__device__ float g_scratch[1500000];
#define OFF_PA       0        // 32*768
#define OFF_U        24576    // 32*768
#define OFF_LOGITS   49152    // 32*2048
#define OFF_MPART    114688   // 32*16*3 = 1536
#define OFF_LPART    116224   // 1536
#define OFF_ACCPART  117760   // 32*16*3*768 = 1179648
#define OFF_XFUSE    1297408  // 64*1536 = 98304
#define OFF_LIN      1395712  // 128*768 = 98304 (pa_lin | cq_lin | fuse_lin) -> total 1494016

// ---------------- f32x2 helpers ----------------
__device__ __forceinline__ unsigned long long pack2(float lo, float hi) {
    unsigned long long r;
    asm("mov.b64 %0,{%1,%2};" : "=l"(r) : "f"(lo), "f"(hi));
    return r;
}
__device__ __forceinline__ void unpack2(unsigned long long v, float& lo, float& hi) {
    asm("mov.b64 {%0,%1},%2;" : "=f"(lo), "=f"(hi) : "l"(v));
}
__device__ __forceinline__ void fma2(unsigned long long& d, unsigned long long a,
                                     unsigned long long b) {
    asm("fma.rn.f32x2 %0,%1,%2,%0;" : "+l"(d) : "l"(a), "l"(b));
}
__device__ __forceinline__ void mul2(unsigned long long& d, unsigned long long a) {
    asm("mul.rn.f32x2 %0,%0,%1;" : "+l"(d) : "l"(a));
}
__device__ __forceinline__ unsigned long long lds64(uint32_t addr) {
    unsigned long long v;
    asm volatile("ld.shared.b64 %0,[%1];" : "=l"(v) : "r"(addr));
    return v;
}

// ---------------- reductions ----------------
__device__ __forceinline__ float block_sum256(float v, float* red) {
    int lane = threadIdx.x & 31, w = threadIdx.x >> 5;
#pragma unroll
    for (int o = 16; o; o >>= 1) v += __shfl_down_sync(0xffffffffu, v, o);
    if (lane == 0) red[w] = v;
    __syncthreads();
    if (w == 0) {
        float x = (lane < 8) ? red[lane] : 0.f;
#pragma unroll
        for (int o = 4; o; o >>= 1) x += __shfl_down_sync(0xffffffffu, x, o);
        if (lane == 0) red[0] = x;
    }
    __syncthreads();
    float r = red[0];
    __syncthreads();
    return r;
}

__device__ __forceinline__ float block_sum768(float v, float* red) {
    int lane = threadIdx.x & 31, w = threadIdx.x >> 5;
#pragma unroll
    for (int o = 16; o; o >>= 1) v += __shfl_down_sync(0xffffffffu, v, o);
    if (lane == 0) red[w] = v;
    __syncthreads();
    if (w == 0) {
        float x = (lane < 24) ? red[lane] : 0.f;
#pragma unroll
        for (int o = 16; o; o >>= 1) x += __shfl_down_sync(0xffffffffu, x, o);
        if (lane == 0) red[0] = x;
    }
    __syncthreads();
    float r = red[0];
    __syncthreads();
    return r;
}

// ---------------- zero the lin accumulation buffers ----------------
__global__ void k_zero(float* __restrict__ p, int n4) {
    int i = blockIdx.x * 256 + threadIdx.x;
    if (i < n4) ((float4*)p)[i] = make_float4(0.f, 0.f, 0.f, 0.f);
}

// ---------------- weight-streaming split-K GEMM (f32x2) -> atomic accumulate into lin ------
template <int KS, int RACC>
__global__ void k_gemm2(const float* __restrict__ X1, int K1, int s1,
                        const float* __restrict__ X2, int s2,
                        const float* __restrict__ W, int K,
                        float* __restrict__ lin, const int* __restrict__ step_sel) {
    __shared__ __align__(16) float xs[KS * RACC];  // transposed: [kk][r]
    int tid = threadIdx.x;
    int j = blockIdx.x * 256 + tid;
    int k0 = blockIdx.y * KS;
    int r0 = blockIdx.z * RACC;

    const float* Wb = W;
    if (step_sel) Wb += (size_t)(*step_sel) * K * D;

    for (int i = tid; i < KS * RACC; i += 256) {
        int r = i / KS, kk = i - r * KS;
        int k = k0 + kk;
        float v = (k < K1) ? X1[(size_t)(r0 + r) * s1 + k]
                           : X2[(size_t)(r0 + r) * s2 + (k - K1)];
        xs[kk * RACC + r] = v;
    }
    __syncthreads();

    uint32_t xs_sa = (uint32_t)__cvta_generic_to_shared(xs);

    unsigned long long acc2[RACC / 2];
#pragma unroll
    for (int p = 0; p < RACC / 2; p++) acc2[p] = 0ull;

    // UNR must divide KS exactly (OOB otherwise)
    constexpr int UNR = (KS % 16 == 0) ? 16 : 8;
    static_assert(KS % UNR == 0, "UNR must divide KS");
    for (int kk0 = 0; kk0 < KS; kk0 += UNR) {
        float w[UNR];
#pragma unroll
        for (int u = 0; u < UNR; u++) w[u] = Wb[(size_t)(k0 + kk0 + u) * D + j];
#pragma unroll
        for (int u = 0; u < UNR; u++) {
            unsigned long long w2 = pack2(w[u], w[u]);
            uint32_t base = xs_sa + (uint32_t)(kk0 + u) * RACC * 4u;
#pragma unroll
            for (int q = 0; q < RACC / 2; q++) {
                fma2(acc2[q], lds64(base + q * 8u), w2);
            }
        }
    }

    float* dst = lin + (size_t)r0 * D + j;
#pragma unroll
    for (int p = 0; p < RACC / 2; p++) {
        float lo, hi;
        unpack2(acc2[p], lo, hi);
        atomicAdd(&dst[(size_t)(2 * p) * D], lo);
        atomicAdd(&dst[(size_t)(2 * p + 1) * D], hi);
    }
}

// ---------------- bias + LN + ReLU (+mul / fuse split-write) on lin rows ----------------
__global__ void k_reduce_ln(const float* __restrict__ lin,
                            const float* __restrict__ bias, const int* __restrict__ step_sel,
                            float* __restrict__ out,
                            const float* __restrict__ g1, const float* __restrict__ b1,
                            const float* __restrict__ g2, const float* __restrict__ b2,
                            const float* __restrict__ wmul, int fuse_map) {
    __shared__ float red[32];
    int r = blockIdx.x, tid = threadIdx.x;
    const float* bb = bias;
    if (step_sel) bb += (size_t)(*step_sel) * D;

    float a = lin[(size_t)r * D + tid] + bb[tid];

    float su = block_sum768(a, red);
    float mu = su * (1.f / D);
    float dd = a - mu;
    float ss = block_sum768(dd * dd, red);
    float inv = rsqrtf(ss * (1.f / D) + 1e-5f);

    const float* g = g1;
    const float* bv = b1;
    float* dst;
    if (fuse_map) {
        int half = r >> 5, bidx = r & 31;
        dst = out + (size_t)bidx * 1536 + half * 768;
        if (half) { g = g2; bv = b2; }
    } else {
        dst = out + (size_t)r * D;
    }
    float y = fmaxf(dd * inv * g[tid] + bv[tid], 0.f);
    if (wmul) y *= wmul[tid];
    dst[tid] = y;
}

// ---------------- main pass: 32-row tiles, cp.async staging, 2 CTAs/SM, all-SM grid ----------
// grid (32, 16) = 512 CTAs (1.73 waves at 2/SM -> all 148 SMs busy), 4 tiles of 32 rows.
__global__ void k_main(const float* __restrict__ ctx, const float* __restrict__ qm1,
                       const float* __restrict__ qm2, const float* __restrict__ battn,
                       const float* __restrict__ u, float* __restrict__ logits,
                       float* __restrict__ mpart, float* __restrict__ lpart,
                       float* __restrict__ accpart) {
    extern __shared__ __align__(16) float sm[];
    float* ctx_sh   = sm;          // 24576
    float* dot_sh   = sm + 24576;  // 32
    float* pa_sh    = sm + 24608;  // 96
    float* q1_sh    = sm + 24704;  // 32
    float* q2_sh    = sm + 24736;  // 32
    float* scale_sh = sm + 24768;  // 4

    int b = blockIdx.x, ch = blockIdx.y;
    int tid = threadIdx.x;
    int w = tid >> 5, lane = tid & 31;

    float u_reg[24];
    {
        const float* ub = u + (size_t)b * D;
#pragma unroll
        for (int i = 0; i < 24; i++) u_reg[i] = ub[lane + 32 * i];
    }

    unsigned long long acc2[3][2];
#pragma unroll
    for (int t3 = 0; t3 < 3; t3++) { acc2[t3][0] = 0ull; acc2[t3][1] = 0ull; }

    float m_r = -INFINITY, l_r = 0.f;
    const float ba = battn[0];
    const float SC = 0.03608439182435161f;  // 1/sqrt(768)

    uint32_t ctx_sa = (uint32_t)__cvta_generic_to_shared(ctx_sh);
    uint32_t q1_sa  = (uint32_t)__cvta_generic_to_shared(q1_sh);
    uint32_t q2_sa  = (uint32_t)__cvta_generic_to_shared(q2_sh);

    for (int t = 0; t < NTILE; t++) {
        int sbase = ch * (NTILE * TILE) + t * TILE;
        const float4* src = (const float4*)(ctx + ((size_t)b * SLEN + sbase) * D);
#pragma unroll
        for (int i = 0; i < 24; i++) {
            int idx = tid + NTHR * i;
            asm volatile("cp.async.cg.shared.global [%0],[%1],16;"
                         :: "r"(ctx_sa + idx * 16), "l"(src + idx));
        }
        if (tid < 32) {
            asm volatile("cp.async.ca.shared.global [%0],[%1],4;"
                         :: "r"(q1_sa + tid * 4), "l"(qm1 + (size_t)b * SLEN + sbase + tid));
        } else if (tid < 64) {
            asm volatile("cp.async.ca.shared.global [%0],[%1],4;"
                         :: "r"(q2_sa + (tid - 32) * 4),
                            "l"(qm2 + (size_t)b * SLEN + sbase + (tid - 32)));
        }
        asm volatile("cp.async.commit_group;");
        asm volatile("cp.async.wait_group 0;");
        __syncthreads();

        // dots: warp w handles s = 4w..4w+3
#pragma unroll
        for (int q = 0; q < 4; q++) {
            int s = w * 4 + q;
            const float* cp = ctx_sh + s * D;
            float a0 = 0.f, a1 = 0.f;
#pragma unroll
            for (int i = 0; i < 24; i += 2) {
                a0 = fmaf(cp[lane + 32 * i], u_reg[i], a0);
                a1 = fmaf(cp[lane + 32 * (i + 1)], u_reg[i + 1], a1);
            }
            float a = a0 + a1;
#pragma unroll
            for (int o = 16; o; o >>= 1) a += __shfl_down_sync(0xffffffffu, a, o);
            if (lane == 0) dot_sh[s] = a;
        }
        __syncthreads();

        // softmax bookkeeping: warps 0-2 handle mask types; warp 3 writes logits
        if (w < 3) {
            float L = (dot_sh[lane] + ba) * SC;
            float q1 = q1_sh[lane], q2 = q2_sh[lane];
            float qv = (w == 0) ? (q1 + q2) : ((w == 1) ? q1 : q2);
            float lg = (qv > 0.f) ? L : -1e9f;
            float msk = (w == 0) ? 1.f : ((qv > 0.f) ? 1.f : 0.f);
            float mx = lg;
#pragma unroll
            for (int o = 16; o; o >>= 1) mx = fmaxf(mx, __shfl_xor_sync(0xffffffffu, mx, o));
            float mnew = fmaxf(m_r, mx);
            float p = expf(lg - mnew);
            float psv = p;
#pragma unroll
            for (int o = 16; o; o >>= 1) psv += __shfl_xor_sync(0xffffffffu, psv, o);
            float sc = expf(m_r - mnew);
            l_r = l_r * sc + psv;
            m_r = mnew;
            pa_sh[w * 32 + lane] = p * msk;
            if (lane == 0) scale_sh[w] = sc;
        } else if (w == 3) {
            logits[(size_t)b * SLEN + sbase + lane] = (dot_sh[lane] + ba) * SC;
        }
        __syncthreads();

        // accumulate: 192 threads x 4 consecutive cols, f32x2 FMAs
        if (tid < 192) {
            unsigned long long s20 = pack2(scale_sh[0], scale_sh[0]);
            unsigned long long s21 = pack2(scale_sh[1], scale_sh[1]);
            unsigned long long s22 = pack2(scale_sh[2], scale_sh[2]);
            mul2(acc2[0][0], s20); mul2(acc2[0][1], s20);
            mul2(acc2[1][0], s21); mul2(acc2[1][1], s21);
            mul2(acc2[2][0], s22); mul2(acc2[2][1], s22);
            const float4* cb = (const float4*)ctx_sh + tid;
#pragma unroll 4
            for (int s = 0; s < TILE; s++) {
                float4 c = cb[s * (D / 4)];
                unsigned long long c01 = pack2(c.x, c.y);
                unsigned long long c23 = pack2(c.z, c.w);
                unsigned long long p0 = pack2(pa_sh[s], pa_sh[s]);
                unsigned long long p1 = pack2(pa_sh[32 + s], pa_sh[32 + s]);
                unsigned long long p2 = pack2(pa_sh[64 + s], pa_sh[64 + s]);
                fma2(acc2[0][0], c01, p0); fma2(acc2[0][1], c23, p0);
                fma2(acc2[1][0], c01, p1); fma2(acc2[1][1], c23, p1);
                fma2(acc2[2][0], c01, p2); fma2(acc2[2][1], c23, p2);
            }
        }
        __syncthreads();  // ctx_sh reused by next tile's cp.async
    }

    if (tid < 192) {
#pragma unroll
        for (int t3 = 0; t3 < 3; t3++) {
            float4 o;
            unpack2(acc2[t3][0], o.x, o.y);
            unpack2(acc2[t3][1], o.z, o.w);
            ((float4*)(accpart + ((size_t)(b * CHUNKS + ch) * 3 + t3) * D))[tid] = o;
        }
    }
    if (w < 3 && lane == 0) {
        mpart[(b * CHUNKS + ch) * 3 + w] = m_r;
        lpart[(b * CHUNKS + ch) * 3 + w] = l_r;
    }
}

// ---------------- combine partials + l2norm + xfuse + attention maps ----------------
__global__ void k_combine_attn(const float* __restrict__ mpart, const float* __restrict__ lpart,
                               const float* __restrict__ accpart,
                               const float* __restrict__ logits,
                               const float* __restrict__ qm1, const float* __restrict__ qm2,
                               float* __restrict__ xfuse, float* __restrict__ attn_out) {
    __shared__ float red[32];
    int b = blockIdx.x, t = blockIdx.y, tid = threadIdx.x;
    float m = -INFINITY;
#pragma unroll
    for (int c = 0; c < CHUNKS; c++) m = fmaxf(m, mpart[(b * CHUNKS + c) * 3 + t]);
    float l = 0.f;
    float v[3] = {0.f, 0.f, 0.f};
#pragma unroll
    for (int c = 0; c < CHUNKS; c++) {
        float wgt = expf(mpart[(b * CHUNKS + c) * 3 + t] - m);
        l += lpart[(b * CHUNKS + c) * 3 + t] * wgt;
        const float* ap = accpart + ((size_t)(b * CHUNKS + c) * 3 + t) * D;
#pragma unroll
        for (int i = 0; i < 3; i++) v[i] = fmaf(ap[tid + 256 * i], wgt, v[i]);
    }
#pragma unroll
    for (int i = 0; i < 3; i++) v[i] /= l;
    float ss = block_sum256(v[0] * v[0] + v[1] * v[1] + v[2] * v[2], red);
    float inv = 1.f / fmaxf(sqrtf(ss), 1e-12f);
#pragma unroll
    for (int i = 0; i < 3; i++) v[i] *= inv;

    if (t == 0) {
        float* d1 = xfuse + (size_t)b * 1536 + 768;
        float* d2 = xfuse + (size_t)(BATCH + b) * 1536 + 768;
#pragma unroll
        for (int i = 0; i < 3; i++) {
            d1[tid + 256 * i] = v[i];
            d2[tid + 256 * i] = v[i];
        }
    } else {
        float* d1 = (t == 1) ? (xfuse + (size_t)b * 1536) : (xfuse + (size_t)(BATCH + b) * 1536);
#pragma unroll
        for (int i = 0; i < 3; i++) d1[tid + 256 * i] = v[i];
    }

    // attention row for (b, t)
    float invl = 1.f / l;
    float* dst = attn_out + ((size_t)b * 3 + t) * SLEN;
#pragma unroll
    for (int i = 0; i < SLEN / 256; i++) {
        int s = tid + 256 * i;
        size_t idx = (size_t)b * SLEN + s;
        float L = logits[idx];
        float qv = (t == 0) ? (qm1[idx] + qm2[idx]) : ((t == 1) ? qm1[idx] : qm2[idx]);
        float lg = (qv > 0.f) ? L : -1e9f;
        dst[s] = expf(lg - m) * invl;
    }
}

// ---------------- launch ----------------
extern "C" void kernel_launch(void* const* d_in, const int* in_sizes, int n_in,
                              void* d_out, int out_size) {
    const int*   step     = (const int*)d_in[0];
    const float* ctx      = (const float*)d_in[1];
    const float* question = (const float*)d_in[2];
    const float* control  = (const float*)d_in[3];
    const float* qm1      = (const float*)d_in[4];
    const float* qm2      = (const float*)d_in[5];
    const float* W_pos    = (const float*)d_in[8];
    const float* b_pos    = (const float*)d_in[9];
    const float* ln1_g    = (const float*)d_in[10];
    const float* ln1_b    = (const float*)d_in[11];
    const float* W_cq     = (const float*)d_in[12];
    const float* b_cq     = (const float*)d_in[13];
    const float* ln2_g    = (const float*)d_in[14];
    const float* ln2_b    = (const float*)d_in[15];
    const float* W_attn   = (const float*)d_in[16];
    const float* b_attn   = (const float*)d_in[17];
    const float* W_fuse   = (const float*)d_in[18];
    const float* b_fuse   = (const float*)d_in[19];
    const float* ln3_g    = (const float*)d_in[20];
    const float* ln3_b    = (const float*)d_in[21];
    const float* ln4_g    = (const float*)d_in[22];
    const float* ln4_b    = (const float*)d_in[23];
    float* out = (float*)d_out;

    void* sp = nullptr;
    cudaGetSymbolAddress(&sp, g_scratch);
    float* s = (float*)sp;
    float* lin_pa   = s + OFF_LIN;           // 32*768
    float* lin_cq   = s + OFF_LIN + 24576;   // 32*768
    float* lin_fuse = s + OFF_LIN + 49152;   // 64*768

    const int mainSmem = 24772 * 4;  // ~99KB -> 2 CTAs/SM
    cudaFuncSetAttribute(k_main, cudaFuncAttributeMaxDynamicSharedMemorySize, mainSmem);

    // zero all three lin accumulation buffers (128*768 floats = 24576 float4s)
    k_zero<<<96, 256>>>(s + OFF_LIN, 24576);

    // pa = ln_relu(question @ W_pos[step] + b_pos[step])  (48 slices, 576 CTAs, atomic acc)
    k_gemm2<16, 8><<<dim3(3, 48, 4), NTHR>>>(question, 768, 768, nullptr, 0, W_pos, 768,
                                             lin_pa, step);
    k_reduce_ln<<<32, 768>>>(lin_pa, b_pos, step, s + OFF_PA,
                             ln1_g, ln1_b, nullptr, nullptr, nullptr, 0);
    // u = ln_relu([control|pa] @ W_cq + b_cq) * W_attn    (48 slices, 576 CTAs, atomic acc)
    k_gemm2<48, 8><<<dim3(3, 48, 4), NTHR>>>(control, 1536, 1536, s + OFF_PA, 768, W_cq, 2304,
                                             lin_cq, nullptr);
    k_reduce_ln<<<32, 768>>>(lin_cq, b_cq, nullptr, s + OFF_U,
                             ln2_g, ln2_b, nullptr, nullptr, W_attn, 0);
    // main context pass (512 CTAs, all SMs, cp.async staging)
    k_main<<<dim3(BATCH, CHUNKS), NTHR, mainSmem>>>(ctx, qm1, qm2, b_attn, s + OFF_U,
                                                    s + OFF_LOGITS, s + OFF_MPART,
                                                    s + OFF_LPART, s + OFF_ACCPART);
    // combine + l2norm + xfuse + attention maps
    k_combine_attn<<<dim3(BATCH, 3), NTHR>>>(s + OFF_MPART, s + OFF_LPART, s + OFF_ACCPART,
                                             s + OFF_LOGITS, qm1, qm2, s + OFF_XFUSE,
                                             out + BATCH * 1536);
    // ctrl1/ctrl2 = ln_relu(xfuse @ W_fuse + b_fuse) -> out (48 slices, 1152 CTAs, atomic acc)
    k_gemm2<32, 8><<<dim3(3, 48, 8), NTHR>>>(s + OFF_XFUSE, 1536, 1536, nullptr, 0, W_fuse,
                                             1536, lin_fuse, nullptr);
    k_reduce_ln<<<64, 768>>>(lin_fuse, b_fuse, nullptr, out,
                             ln3_g, ln3_b, ln4_g, ln4_b, nullptr, 1);
}

// round 16
// speedup vs baseline: 1.0686x; 1.0488x over previous
#include <cuda_runtime.h>
#include <math.h>
#include <stdint.h>

#define D      768
#define SLEN   2048
#define BATCH  32
#define CHUNKS 16
#define TILE   16
#define NTILE  8
#define NTHR   256

// ---------------- scratch ----------------
__device__ float g_scratch[1500000];
#define OFF_PA       0        // 32*768
#define OFF_U        24576    // 32*768
#define OFF_LOGITS   49152    // 32*2048
#define OFF_LPART    114688   // 32*16*3 = 1536
#define OFF_ACCPART  117760   // 32*16*3*768 = 1179648
#define OFF_XFUSE    1297408  // 64*1536 = 98304
#define OFF_LIN      1395712  // 128*768 = 98304

// ---------------- f32x2 helpers ----------------
__device__ __forceinline__ unsigned long long pack2(float lo, float hi) {
    unsigned long long r;
    asm("mov.b64 %0,{%1,%2};" : "=l"(r) : "f"(lo), "f"(hi));
    return r;
}
__device__ __forceinline__ void unpack2(unsigned long long v, float& lo, float& hi) {
    asm("mov.b64 {%0,%1},%2;" : "=f"(lo), "=f"(hi) : "l"(v));
}
__device__ __forceinline__ void fma2(unsigned long long& d, unsigned long long a,
                                     unsigned long long b) {
    asm("fma.rn.f32x2 %0,%1,%2,%0;" : "+l"(d) : "l"(a), "l"(b));
}

// ---------------- reductions ----------------
__device__ __forceinline__ float block_sum256(float v, float* red) {
    int lane = threadIdx.x & 31, w = threadIdx.x >> 5;
#pragma unroll
    for (int o = 16; o; o >>= 1) v += __shfl_down_sync(0xffffffffu, v, o);
    if (lane == 0) red[w] = v;
    __syncthreads();
    if (w == 0) {
        float x = (lane < 8) ? red[lane] : 0.f;
#pragma unroll
        for (int o = 4; o; o >>= 1) x += __shfl_down_sync(0xffffffffu, x, o);
        if (lane == 0) red[0] = x;
    }
    __syncthreads();
    float r = red[0];
    __syncthreads();
    return r;
}

__device__ __forceinline__ float block_sum768(float v, float* red) {
    int lane = threadIdx.x & 31, w = threadIdx.x >> 5;
#pragma unroll
    for (int o = 16; o; o >>= 1) v += __shfl_down_sync(0xffffffffu, v, o);
    if (lane == 0) red[w] = v;
    __syncthreads();
    if (w == 0) {
        float x = (lane < 24) ? red[lane] : 0.f;
#pragma unroll
        for (int o = 16; o; o >>= 1) x += __shfl_down_sync(0xffffffffu, x, o);
        if (lane == 0) red[0] = x;
    }
    __syncthreads();
    float r = red[0];
    __syncthreads();
    return r;
}

// ---------------- zero the lin accumulation buffers ----------------
__global__ void k_zero(float* __restrict__ p, int n4) {
    int i = blockIdx.x * 256 + threadIdx.x;
    if (i < n4) ((float4*)p)[i] = make_float4(0.f, 0.f, 0.f, 0.f);
}

// ---------------- weight-streaming split-K GEMM (f32x2) -> atomic accumulate into lin ------
template <int KS, int RACC>
__global__ void k_gemm2(const float* __restrict__ X1, int K1, int s1,
                        const float* __restrict__ X2, int s2,
                        const float* __restrict__ W, int K,
                        float* __restrict__ lin, const int* __restrict__ step_sel) {
    __shared__ __align__(16) float xs[KS * RACC];  // transposed: [kk][r]
    int tid = threadIdx.x;
    int j = blockIdx.x * 256 + tid;
    int k0 = blockIdx.y * KS;
    int r0 = blockIdx.z * RACC;

    const float* Wb = W;
    if (step_sel) Wb += (size_t)(*step_sel) * K * D;

    for (int i = tid; i < KS * RACC; i += 256) {
        int r = i / KS, kk = i - r * KS;
        int k = k0 + kk;
        float v = (k < K1) ? X1[(size_t)(r0 + r) * s1 + k]
                           : X2[(size_t)(r0 + r) * s2 + (k - K1)];
        xs[kk * RACC + r] = v;
    }
    __syncthreads();

    unsigned long long acc2[RACC / 2];
#pragma unroll
    for (int p = 0; p < RACC / 2; p++) acc2[p] = 0ull;

    constexpr int UNR = (KS % 16 == 0) ? 16 : 8;
    static_assert(KS % UNR == 0, "UNR must divide KS");
    for (int kk0 = 0; kk0 < KS; kk0 += UNR) {
        float w[UNR];
#pragma unroll
        for (int u = 0; u < UNR; u++) w[u] = Wb[(size_t)(k0 + kk0 + u) * D + j];
#pragma unroll
        for (int u = 0; u < UNR; u++) {
            unsigned long long w2 = pack2(w[u], w[u]);
            const float4* xr = (const float4*)(xs + (kk0 + u) * RACC);
#pragma unroll
            for (int p = 0; p < RACC / 4; p++) {
                float4 xv = xr[p];
                fma2(acc2[2 * p], pack2(xv.x, xv.y), w2);
                fma2(acc2[2 * p + 1], pack2(xv.z, xv.w), w2);
            }
        }
    }

    float* dst = lin + (size_t)r0 * D + j;
#pragma unroll
    for (int p = 0; p < RACC / 2; p++) {
        float lo, hi;
        unpack2(acc2[p], lo, hi);
        atomicAdd(&dst[(size_t)(2 * p) * D], lo);
        atomicAdd(&dst[(size_t)(2 * p + 1) * D], hi);
    }
}

// ---------------- bias + LN + ReLU (+mul / fuse split-write) on lin rows ----------------
__global__ void k_reduce_ln(const float* __restrict__ lin,
                            const float* __restrict__ bias, const int* __restrict__ step_sel,
                            float* __restrict__ out,
                            const float* __restrict__ g1, const float* __restrict__ b1,
                            const float* __restrict__ g2, const float* __restrict__ b2,
                            const float* __restrict__ wmul, int fuse_map) {
    __shared__ float red[32];
    int r = blockIdx.x, tid = threadIdx.x;
    const float* bb = bias;
    if (step_sel) bb += (size_t)(*step_sel) * D;

    float a = lin[(size_t)r * D + tid] + bb[tid];

    float su = block_sum768(a, red);
    float mu = su * (1.f / D);
    float dd = a - mu;
    float ss = block_sum768(dd * dd, red);
    float inv = rsqrtf(ss * (1.f / D) + 1e-5f);

    const float* g = g1;
    const float* bv = b1;
    float* dst;
    if (fuse_map) {
        int half = r >> 5, bidx = r & 31;
        dst = out + (size_t)bidx * 1536 + half * 768;
        if (half) { g = g2; bv = b2; }
    } else {
        dst = out + (size_t)r * D;
    }
    float y = fmaxf(dd * inv * g[tid] + bv[tid], 0.f);
    if (wmul) y *= wmul[tid];
    dst[tid] = y;
}

// ---------------- main pass: 16-row tiles, DOUBLE-buffered cp.async, 2 CTAs/SM, all SMs ----
// grid (32, 16) = 512 CTAs, 8 tiles of 16 rows. No-max softmax: p = exp(logit) directly
// (|logit| is O(1); masked -> exp(-1e9) = 0). No per-tile shuffles, no accumulator rescale.
__global__ void k_main(const float* __restrict__ ctx, const float* __restrict__ qm1,
                       const float* __restrict__ qm2, const float* __restrict__ battn,
                       const float* __restrict__ u, float* __restrict__ logits,
                       float* __restrict__ lpart, float* __restrict__ accpart) {
    extern __shared__ __align__(16) float sm[];
    // ctx[2][12288] | q1[2][16] | q2[2][16] | dot[16] | pa[48]
    float* q1b    = sm + 24576;
    float* q2b    = sm + 24608;
    float* dot_sh = sm + 24640;
    float* pa_sh  = sm + 24656;

    int b = blockIdx.x, ch = blockIdx.y;
    int tid = threadIdx.x;
    int w = tid >> 5, lane = tid & 31;

    float u_reg[24];
    {
        const float* ub = u + (size_t)b * D;
#pragma unroll
        for (int i = 0; i < 24; i++) u_reg[i] = ub[lane + 32 * i];
    }

    unsigned long long acc2[3][2];
#pragma unroll
    for (int t3 = 0; t3 < 3; t3++) { acc2[t3][0] = 0ull; acc2[t3][1] = 0ull; }

    float l_r = 0.f;
    const float ba = battn[0];
    const float SC = 0.03608439182435161f;  // 1/sqrt(768)

    uint32_t sm_sa = (uint32_t)__cvta_generic_to_shared(sm);
    uint32_t q1_sa = (uint32_t)__cvta_generic_to_shared(q1b);
    uint32_t q2_sa = (uint32_t)__cvta_generic_to_shared(q2b);

#define ISSUE_TILE(T)                                                                      \
    do {                                                                                   \
        int _t = (T);                                                                      \
        int _buf = _t & 1;                                                                 \
        int _sbase = ch * (NTILE * TILE) + _t * TILE;                                      \
        const float4* _src = (const float4*)(ctx + ((size_t)b * SLEN + _sbase) * D);       \
        uint32_t _dst = sm_sa + (uint32_t)_buf * 12288u * 4u;                              \
        _Pragma("unroll")                                                                  \
        for (int _i = 0; _i < 12; _i++) {                                                  \
            int _idx = tid + NTHR * _i;                                                    \
            asm volatile("cp.async.cg.shared.global [%0],[%1],16;"                         \
                         :: "r"(_dst + _idx * 16), "l"(_src + _idx));                      \
        }                                                                                  \
        if (tid < TILE) {                                                                  \
            asm volatile("cp.async.ca.shared.global [%0],[%1],4;"                          \
                         :: "r"(q1_sa + _buf * 64 + tid * 4),                              \
                            "l"(qm1 + (size_t)b * SLEN + _sbase + tid));                   \
        } else if (tid < 2 * TILE) {                                                       \
            asm volatile("cp.async.ca.shared.global [%0],[%1],4;"                          \
                         :: "r"(q2_sa + _buf * 64 + (tid - TILE) * 4),                     \
                            "l"(qm2 + (size_t)b * SLEN + _sbase + (tid - TILE)));          \
        }                                                                                  \
        asm volatile("cp.async.commit_group;");                                            \
    } while (0)

    ISSUE_TILE(0);

    for (int t = 0; t < NTILE; t++) {
        if (t + 1 < NTILE) {
            ISSUE_TILE(t + 1);
            asm volatile("cp.async.wait_group 1;");
        } else {
            asm volatile("cp.async.wait_group 0;");
        }
        __syncthreads();

        int buf = t & 1;
        float* ctx_sh = sm + buf * 12288;
        int sbase = ch * (NTILE * TILE) + t * TILE;

        // dots: warp w handles s = 2w, 2w+1
#pragma unroll
        for (int q = 0; q < 2; q++) {
            int s = w * 2 + q;
            const float* cp = ctx_sh + s * D;
            float a0 = 0.f, a1 = 0.f;
#pragma unroll
            for (int i = 0; i < 24; i += 2) {
                a0 = fmaf(cp[lane + 32 * i], u_reg[i], a0);
                a1 = fmaf(cp[lane + 32 * (i + 1)], u_reg[i + 1], a1);
            }
            float a = a0 + a1;
#pragma unroll
            for (int o = 16; o; o >>= 1) a += __shfl_down_sync(0xffffffffu, a, o);
            if (lane == 0) dot_sh[s] = a;
        }
        __syncthreads();

        // no-max softmax: p = exp(lg) directly; masked -> exactly 0
        if (w < 3) {
            if (lane < TILE) {
                float L = (dot_sh[lane] + ba) * SC;
                float q1 = q1b[buf * TILE + lane], q2 = q2b[buf * TILE + lane];
                float qv = (w == 0) ? (q1 + q2) : ((w == 1) ? q1 : q2);
                float p = (qv > 0.f) ? expf(L) : 0.f;
                l_r += p;
                pa_sh[w * TILE + lane] = p;
            }
        } else if (w == 3 && lane < TILE) {
            logits[(size_t)b * SLEN + sbase + lane] = (dot_sh[lane] + ba) * SC;
        }
        __syncthreads();

        // accumulate: 192 threads x 4 consecutive cols, f32x2 FMAs, no rescale
        if (tid < 192) {
            const float4* cb = (const float4*)ctx_sh + tid;
#pragma unroll 4
            for (int s = 0; s < TILE; s++) {
                float4 c = cb[s * (D / 4)];
                unsigned long long c01 = pack2(c.x, c.y);
                unsigned long long c23 = pack2(c.z, c.w);
                unsigned long long p0 = pack2(pa_sh[s], pa_sh[s]);
                unsigned long long p1 = pack2(pa_sh[TILE + s], pa_sh[TILE + s]);
                unsigned long long p2 = pack2(pa_sh[2 * TILE + s], pa_sh[2 * TILE + s]);
                fma2(acc2[0][0], c01, p0); fma2(acc2[0][1], c23, p0);
                fma2(acc2[1][0], c01, p1); fma2(acc2[1][1], c23, p1);
                fma2(acc2[2][0], c01, p2); fma2(acc2[2][1], c23, p2);
            }
        }
        __syncthreads();  // buf reused by issue(t+2)
    }

    if (tid < 192) {
#pragma unroll
        for (int t3 = 0; t3 < 3; t3++) {
            float4 o;
            unpack2(acc2[t3][0], o.x, o.y);
            unpack2(acc2[t3][1], o.z, o.w);
            ((float4*)(accpart + ((size_t)(b * CHUNKS + ch) * 3 + t3) * D))[tid] = o;
        }
    }
    if (w < 3) {
        // lanes >= TILE hold 0
#pragma unroll
        for (int o = 16; o; o >>= 1) l_r += __shfl_down_sync(0xffffffffu, l_r, o);
        if (lane == 0) lpart[(b * CHUNKS + ch) * 3 + w] = l_r;
    }
#undef ISSUE_TILE
}

// ---------------- combine partials + l2norm + xfuse + attention maps (no-max) ------------
__global__ void k_combine_attn(const float* __restrict__ lpart,
                               const float* __restrict__ accpart,
                               const float* __restrict__ logits,
                               const float* __restrict__ qm1, const float* __restrict__ qm2,
                               float* __restrict__ xfuse, float* __restrict__ attn_out) {
    __shared__ float red[32];
    int b = blockIdx.x, t = blockIdx.y, tid = threadIdx.x;
    float l = 0.f;
    float v[3] = {0.f, 0.f, 0.f};
#pragma unroll
    for (int c = 0; c < CHUNKS; c++) {
        l += lpart[(b * CHUNKS + c) * 3 + t];
        const float* ap = accpart + ((size_t)(b * CHUNKS + c) * 3 + t) * D;
#pragma unroll
        for (int i = 0; i < 3; i++) v[i] += ap[tid + 256 * i];
    }
#pragma unroll
    for (int i = 0; i < 3; i++) v[i] /= l;
    float ss = block_sum256(v[0] * v[0] + v[1] * v[1] + v[2] * v[2], red);
    float inv = 1.f / fmaxf(sqrtf(ss), 1e-12f);
#pragma unroll
    for (int i = 0; i < 3; i++) v[i] *= inv;

    if (t == 0) {
        float* d1 = xfuse + (size_t)b * 1536 + 768;
        float* d2 = xfuse + (size_t)(BATCH + b) * 1536 + 768;
#pragma unroll
        for (int i = 0; i < 3; i++) {
            d1[tid + 256 * i] = v[i];
            d2[tid + 256 * i] = v[i];
        }
    } else {
        float* d1 = (t == 1) ? (xfuse + (size_t)b * 1536) : (xfuse + (size_t)(BATCH + b) * 1536);
#pragma unroll
        for (int i = 0; i < 3; i++) d1[tid + 256 * i] = v[i];
    }

    float invl = 1.f / l;
    float* dst = attn_out + ((size_t)b * 3 + t) * SLEN;
#pragma unroll
    for (int i = 0; i < SLEN / 256; i++) {
        int s = tid + 256 * i;
        size_t idx = (size_t)b * SLEN + s;
        float L = logits[idx];
        float qv = (t == 0) ? (qm1[idx] + qm2[idx]) : ((t == 1) ? qm1[idx] : qm2[idx]);
        dst[s] = (qv > 0.f) ? expf(L) * invl : 0.f;
    }
}

// ---------------- launch ----------------
extern "C" void kernel_launch(void* const* d_in, const int* in_sizes, int n_in,
                              void* d_out, int out_size) {
    const int*   step     = (const int*)d_in[0];
    const float* ctx      = (const float*)d_in[1];
    const float* question = (const float*)d_in[2];
    const float* control  = (const float*)d_in[3];
    const float* qm1      = (const float*)d_in[4];
    const float* qm2      = (const float*)d_in[5];
    const float* W_pos    = (const float*)d_in[8];
    const float* b_pos    = (const float*)d_in[9];
    const float* ln1_g    = (const float*)d_in[10];
    const float* ln1_b    = (const float*)d_in[11];
    const float* W_cq     = (const float*)d_in[12];
    const float* b_cq     = (const float*)d_in[13];
    const float* ln2_g    = (const float*)d_in[14];
    const float* ln2_b    = (const float*)d_in[15];
    const float* W_attn   = (const float*)d_in[16];
    const float* b_attn   = (const float*)d_in[17];
    const float* W_fuse   = (const float*)d_in[18];
    const float* b_fuse   = (const float*)d_in[19];
    const float* ln3_g    = (const float*)d_in[20];
    const float* ln3_b    = (const float*)d_in[21];
    const float* ln4_g    = (const float*)d_in[22];
    const float* ln4_b    = (const float*)d_in[23];
    float* out = (float*)d_out;

    void* sp = nullptr;
    cudaGetSymbolAddress(&sp, g_scratch);
    float* s = (float*)sp;
    float* lin_pa   = s + OFF_LIN;
    float* lin_cq   = s + OFF_LIN + 24576;
    float* lin_fuse = s + OFF_LIN + 49152;

    const int mainSmem = 24704 * 4;  // ~98.8KB -> 2 CTAs/SM
    cudaFuncSetAttribute(k_main, cudaFuncAttributeMaxDynamicSharedMemorySize, mainSmem);

    k_zero<<<96, 256>>>(s + OFF_LIN, 24576);

    // pa = ln_relu(question @ W_pos[step] + b_pos[step])  (48 slices)
    k_gemm2<16, 8><<<dim3(3, 48, 4), NTHR>>>(question, 768, 768, nullptr, 0, W_pos, 768,
                                             lin_pa, step);
    k_reduce_ln<<<32, 768>>>(lin_pa, b_pos, step, s + OFF_PA,
                             ln1_g, ln1_b, nullptr, nullptr, nullptr, 0);
    // u = ln_relu([control|pa] @ W_cq + b_cq) * W_attn    (48 slices)
    k_gemm2<48, 8><<<dim3(3, 48, 4), NTHR>>>(control, 1536, 1536, s + OFF_PA, 768, W_cq, 2304,
                                             lin_cq, nullptr);
    k_reduce_ln<<<32, 768>>>(lin_cq, b_cq, nullptr, s + OFF_U,
                             ln2_g, ln2_b, nullptr, nullptr, W_attn, 0);
    // main context pass (512 CTAs, dbl-buffered, 2 CTAs/SM, no-max softmax)
    k_main<<<dim3(BATCH, CHUNKS), NTHR, mainSmem>>>(ctx, qm1, qm2, b_attn, s + OFF_U,
                                                    s + OFF_LOGITS, s + OFF_LPART,
                                                    s + OFF_ACCPART);
    // combine + l2norm + xfuse + attention maps
    k_combine_attn<<<dim3(BATCH, 3), NTHR>>>(s + OFF_LPART, s + OFF_ACCPART, s + OFF_LOGITS,
                                             qm1, qm2, s + OFF_XFUSE, out + BATCH * 1536);
    // ctrl1/ctrl2 = ln_relu(xfuse @ W_fuse + b_fuse) -> out (48 slices)
    k_gemm2<32, 8><<<dim3(3, 48, 8), NTHR>>>(s + OFF_XFUSE, 1536, 1536, nullptr, 0, W_fuse,
                                             1536, lin_fuse, nullptr);
    k_reduce_ln<<<64, 768>>>(lin_fuse, b_fuse, nullptr, out,
                             ln3_g, ln3_b, ln4_g, ln4_b, nullptr, 1);
}

// round 17
// speedup vs baseline: 1.0769x; 1.0078x over previous
#include <cuda_runtime.h>
#include <math.h>
#include <stdint.h>

#define D      768
#define SLEN   2048
#define BATCH  32
#define CHUNKS 16
#define TILE   16
#define NTILE  8
#define NTHR   256

// ---------------- scratch ----------------
__device__ float g_scratch[1500000];
#define OFF_PA       0        // 32*768
#define OFF_U        24576    // 32*768
#define OFF_LOGITS   49152    // 32*2048
#define OFF_LPART    114688   // 32*16*3 = 1536
#define OFF_ACCPART  117760   // 32*16*3*768 = 1179648
#define OFF_XFUSE    1297408  // 64*1536 = 98304
#define OFF_LIN      1395712  // 128*768 = 98304

// ---------------- f32x2 helpers ----------------
__device__ __forceinline__ unsigned long long pack2(float lo, float hi) {
    unsigned long long r;
    asm("mov.b64 %0,{%1,%2};" : "=l"(r) : "f"(lo), "f"(hi));
    return r;
}
__device__ __forceinline__ void unpack2(unsigned long long v, float& lo, float& hi) {
    asm("mov.b64 {%0,%1},%2;" : "=f"(lo), "=f"(hi) : "l"(v));
}
__device__ __forceinline__ void fma2(unsigned long long& d, unsigned long long a,
                                     unsigned long long b) {
    asm("fma.rn.f32x2 %0,%1,%2,%0;" : "+l"(d) : "l"(a), "l"(b));
}

// ---------------- reductions ----------------
__device__ __forceinline__ float block_sum256(float v, float* red) {
    int lane = threadIdx.x & 31, w = threadIdx.x >> 5;
#pragma unroll
    for (int o = 16; o; o >>= 1) v += __shfl_down_sync(0xffffffffu, v, o);
    if (lane == 0) red[w] = v;
    __syncthreads();
    if (w == 0) {
        float x = (lane < 8) ? red[lane] : 0.f;
#pragma unroll
        for (int o = 4; o; o >>= 1) x += __shfl_down_sync(0xffffffffu, x, o);
        if (lane == 0) red[0] = x;
    }
    __syncthreads();
    float r = red[0];
    __syncthreads();
    return r;
}

__device__ __forceinline__ float block_sum768(float v, float* red) {
    int lane = threadIdx.x & 31, w = threadIdx.x >> 5;
#pragma unroll
    for (int o = 16; o; o >>= 1) v += __shfl_down_sync(0xffffffffu, v, o);
    if (lane == 0) red[w] = v;
    __syncthreads();
    if (w == 0) {
        float x = (lane < 24) ? red[lane] : 0.f;
#pragma unroll
        for (int o = 16; o; o >>= 1) x += __shfl_down_sync(0xffffffffu, x, o);
        if (lane == 0) red[0] = x;
    }
    __syncthreads();
    float r = red[0];
    __syncthreads();
    return r;
}

// ---------------- zero the lin accumulation buffers ----------------
__global__ void k_zero(float* __restrict__ p, int n4) {
    int i = blockIdx.x * 256 + threadIdx.x;
    if (i < n4) ((float4*)p)[i] = make_float4(0.f, 0.f, 0.f, 0.f);
}

// ---------------- weight-streaming split-K GEMM (f32x2) -> atomic accumulate into lin ------
template <int KS, int RACC>
__global__ void k_gemm2(const float* __restrict__ X1, int K1, int s1,
                        const float* __restrict__ X2, int s2,
                        const float* __restrict__ W, int K,
                        float* __restrict__ lin, const int* __restrict__ step_sel) {
    __shared__ __align__(16) float xs[KS * RACC];  // transposed: [kk][r]
    int tid = threadIdx.x;
    int j = blockIdx.x * 256 + tid;
    int k0 = blockIdx.y * KS;
    int r0 = blockIdx.z * RACC;

    const float* Wb = W;
    if (step_sel) Wb += (size_t)(*step_sel) * K * D;

    for (int i = tid; i < KS * RACC; i += 256) {
        int r = i / KS, kk = i - r * KS;
        int k = k0 + kk;
        float v = (k < K1) ? X1[(size_t)(r0 + r) * s1 + k]
                           : X2[(size_t)(r0 + r) * s2 + (k - K1)];
        xs[kk * RACC + r] = v;
    }
    __syncthreads();

    unsigned long long acc2[RACC / 2];
#pragma unroll
    for (int p = 0; p < RACC / 2; p++) acc2[p] = 0ull;

    constexpr int UNR = (KS % 16 == 0) ? 16 : 8;
    static_assert(KS % UNR == 0, "UNR must divide KS");
    for (int kk0 = 0; kk0 < KS; kk0 += UNR) {
        float w[UNR];
#pragma unroll
        for (int u = 0; u < UNR; u++) w[u] = Wb[(size_t)(k0 + kk0 + u) * D + j];
#pragma unroll
        for (int u = 0; u < UNR; u++) {
            unsigned long long w2 = pack2(w[u], w[u]);
            const float4* xr = (const float4*)(xs + (kk0 + u) * RACC);
#pragma unroll
            for (int p = 0; p < RACC / 4; p++) {
                float4 xv = xr[p];
                fma2(acc2[2 * p], pack2(xv.x, xv.y), w2);
                fma2(acc2[2 * p + 1], pack2(xv.z, xv.w), w2);
            }
        }
    }

    float* dst = lin + (size_t)r0 * D + j;
#pragma unroll
    for (int p = 0; p < RACC / 2; p++) {
        float lo, hi;
        unpack2(acc2[p], lo, hi);
        atomicAdd(&dst[(size_t)(2 * p) * D], lo);
        atomicAdd(&dst[(size_t)(2 * p + 1) * D], hi);
    }
}

// ---------------- bias + LN + ReLU (+mul / fuse split-write) on lin rows ----------------
__global__ void k_reduce_ln(const float* __restrict__ lin,
                            const float* __restrict__ bias, const int* __restrict__ step_sel,
                            float* __restrict__ out,
                            const float* __restrict__ g1, const float* __restrict__ b1,
                            const float* __restrict__ g2, const float* __restrict__ b2,
                            const float* __restrict__ wmul, int fuse_map) {
    __shared__ float red[32];
    int r = blockIdx.x, tid = threadIdx.x;
    const float* bb = bias;
    if (step_sel) bb += (size_t)(*step_sel) * D;

    float a = lin[(size_t)r * D + tid] + bb[tid];

    float su = block_sum768(a, red);
    float mu = su * (1.f / D);
    float dd = a - mu;
    float ss = block_sum768(dd * dd, red);
    float inv = rsqrtf(ss * (1.f / D) + 1e-5f);

    const float* g = g1;
    const float* bv = b1;
    float* dst;
    if (fuse_map) {
        int half = r >> 5, bidx = r & 31;
        dst = out + (size_t)bidx * 1536 + half * 768;
        if (half) { g = g2; bv = b2; }
    } else {
        dst = out + (size_t)r * D;
    }
    float y = fmaxf(dd * inv * g[tid] + bv[tid], 0.f);
    if (wmul) y *= wmul[tid];
    dst[tid] = y;
}

// ---------------- main pass: warp-owned softmax, 2 barriers/tile, dbl-buffered ------------
// grid (32, 16) = 512 CTAs, 8 tiles of 16 rows, 2 CTAs/SM. Warp w owns rows 2w, 2w+1:
// computes their dots AND their masked p's (one expf per row) with no cross-warp handoff.
// Per-tile: [wait; sync; issue(t+1)] dots+softmax [sync] accumulate — top sync of the next
// iteration doubles as the buffer-reuse guard.
__global__ void k_main(const float* __restrict__ ctx, const float* __restrict__ qm1,
                       const float* __restrict__ qm2, const float* __restrict__ battn,
                       const float* __restrict__ u, float* __restrict__ logits,
                       float* __restrict__ lpart, float* __restrict__ accpart) {
    extern __shared__ __align__(16) float sm[];
    // ctx[2][12288] | q1[2][16] | q2[2][16] | pa[48] | lw[24]
    float* q1b   = sm + 24576;
    float* q2b   = sm + 24608;
    float* pa_sh = sm + 24640;
    float* lw_sh = sm + 24688;

    int b = blockIdx.x, ch = blockIdx.y;
    int tid = threadIdx.x;
    int w = tid >> 5, lane = tid & 31;

    float u_reg[24];
    {
        const float* ub = u + (size_t)b * D;
#pragma unroll
        for (int i = 0; i < 24; i++) u_reg[i] = ub[lane + 32 * i];
    }

    unsigned long long acc2[3][2];
#pragma unroll
    for (int t3 = 0; t3 < 3; t3++) { acc2[t3][0] = 0ull; acc2[t3][1] = 0ull; }

    float l0 = 0.f, l1 = 0.f, l2 = 0.f;
    const float ba = battn[0];
    const float SC = 0.03608439182435161f;  // 1/sqrt(768)

    uint32_t sm_sa = (uint32_t)__cvta_generic_to_shared(sm);
    uint32_t q1_sa = (uint32_t)__cvta_generic_to_shared(q1b);
    uint32_t q2_sa = (uint32_t)__cvta_generic_to_shared(q2b);

#define ISSUE_TILE(T)                                                                      \
    do {                                                                                   \
        int _t = (T);                                                                      \
        int _buf = _t & 1;                                                                 \
        int _sbase = ch * (NTILE * TILE) + _t * TILE;                                      \
        const float4* _src = (const float4*)(ctx + ((size_t)b * SLEN + _sbase) * D);       \
        uint32_t _dst = sm_sa + (uint32_t)_buf * 12288u * 4u;                              \
        _Pragma("unroll")                                                                  \
        for (int _i = 0; _i < 12; _i++) {                                                  \
            int _idx = tid + NTHR * _i;                                                    \
            asm volatile("cp.async.cg.shared.global [%0],[%1],16;"                         \
                         :: "r"(_dst + _idx * 16), "l"(_src + _idx));                      \
        }                                                                                  \
        if (tid < TILE) {                                                                  \
            asm volatile("cp.async.ca.shared.global [%0],[%1],4;"                          \
                         :: "r"(q1_sa + _buf * 64 + tid * 4),                              \
                            "l"(qm1 + (size_t)b * SLEN + _sbase + tid));                   \
        } else if (tid < 2 * TILE) {                                                       \
            asm volatile("cp.async.ca.shared.global [%0],[%1],4;"                          \
                         :: "r"(q2_sa + _buf * 64 + (tid - TILE) * 4),                     \
                            "l"(qm2 + (size_t)b * SLEN + _sbase + (tid - TILE)));          \
        }                                                                                  \
        asm volatile("cp.async.commit_group;");                                            \
    } while (0)

    ISSUE_TILE(0);

    for (int t = 0; t < NTILE; t++) {
        asm volatile("cp.async.wait_group 0;");
        __syncthreads();  // cp.async visibility + buffer-reuse guard for previous accumulate
        if (t + 1 < NTILE) ISSUE_TILE(t + 1);

        int buf = t & 1;
        float* ctx_sh = sm + buf * 12288;
        int sbase = ch * (NTILE * TILE) + t * TILE;

        // dots for warp-owned rows 2w, 2w+1
        float aRow[2];
#pragma unroll
        for (int q = 0; q < 2; q++) {
            int s = w * 2 + q;
            const float* cp = ctx_sh + s * D;
            float a0 = 0.f, a1 = 0.f;
#pragma unroll
            for (int i = 0; i < 24; i += 2) {
                a0 = fmaf(cp[lane + 32 * i], u_reg[i], a0);
                a1 = fmaf(cp[lane + 32 * (i + 1)], u_reg[i + 1], a1);
            }
            float a = a0 + a1;
#pragma unroll
            for (int o = 16; o; o >>= 1) a += __shfl_down_sync(0xffffffffu, a, o);
            aRow[q] = a;  // valid on lane 0
        }
        // warp-owned softmax: lane 0 finishes its two rows (one expf per row)
        if (lane == 0) {
#pragma unroll
            for (int q = 0; q < 2; q++) {
                int row = w * 2 + q;
                float L = (aRow[q] + ba) * SC;
                float m1 = q1b[buf * TILE + row], m2 = q2b[buf * TILE + row];
                float e = expf(L);
                float p0 = (m1 + m2 > 0.f) ? e : 0.f;
                float p1 = (m1 > 0.f) ? e : 0.f;
                float p2 = (m2 > 0.f) ? e : 0.f;
                pa_sh[row] = p0;
                pa_sh[TILE + row] = p1;
                pa_sh[2 * TILE + row] = p2;
                l0 += p0; l1 += p1; l2 += p2;
                logits[(size_t)b * SLEN + sbase + row] = L;
            }
        }
        __syncthreads();  // pa_sh visible to accumulate

        // accumulate: 192 threads x 4 consecutive cols, f32x2 FMAs
        if (tid < 192) {
            const float4* cb = (const float4*)ctx_sh + tid;
#pragma unroll 4
            for (int s = 0; s < TILE; s++) {
                float4 c = cb[s * (D / 4)];
                unsigned long long c01 = pack2(c.x, c.y);
                unsigned long long c23 = pack2(c.z, c.w);
                unsigned long long p0 = pack2(pa_sh[s], pa_sh[s]);
                unsigned long long p1 = pack2(pa_sh[TILE + s], pa_sh[TILE + s]);
                unsigned long long p2 = pack2(pa_sh[2 * TILE + s], pa_sh[2 * TILE + s]);
                fma2(acc2[0][0], c01, p0); fma2(acc2[0][1], c23, p0);
                fma2(acc2[1][0], c01, p1); fma2(acc2[1][1], c23, p1);
                fma2(acc2[2][0], c01, p2); fma2(acc2[2][1], c23, p2);
            }
        }
        // no end barrier: next iteration's top sync guards buffer reuse
    }

    if (tid < 192) {
#pragma unroll
        for (int t3 = 0; t3 < 3; t3++) {
            float4 o;
            unpack2(acc2[t3][0], o.x, o.y);
            unpack2(acc2[t3][1], o.z, o.w);
            ((float4*)(accpart + ((size_t)(b * CHUNKS + ch) * 3 + t3) * D))[tid] = o;
        }
    }
    if (lane == 0) {
        lw_sh[w * 3 + 0] = l0;
        lw_sh[w * 3 + 1] = l1;
        lw_sh[w * 3 + 2] = l2;
    }
    __syncthreads();
    if (tid < 3) {
        float l = 0.f;
#pragma unroll
        for (int ww = 0; ww < 8; ww++) l += lw_sh[ww * 3 + tid];
        lpart[(b * CHUNKS + ch) * 3 + tid] = l;
    }
#undef ISSUE_TILE
}

// ---------------- combine partials + l2norm + xfuse + attention maps (no-max) ------------
__global__ void k_combine_attn(const float* __restrict__ lpart,
                               const float* __restrict__ accpart,
                               const float* __restrict__ logits,
                               const float* __restrict__ qm1, const float* __restrict__ qm2,
                               float* __restrict__ xfuse, float* __restrict__ attn_out) {
    __shared__ float red[32];
    int b = blockIdx.x, t = blockIdx.y, tid = threadIdx.x;
    float l = 0.f;
    float v[3] = {0.f, 0.f, 0.f};
#pragma unroll
    for (int c = 0; c < CHUNKS; c++) {
        l += lpart[(b * CHUNKS + c) * 3 + t];
        const float* ap = accpart + ((size_t)(b * CHUNKS + c) * 3 + t) * D;
#pragma unroll
        for (int i = 0; i < 3; i++) v[i] += ap[tid + 256 * i];
    }
#pragma unroll
    for (int i = 0; i < 3; i++) v[i] /= l;
    float ss = block_sum256(v[0] * v[0] + v[1] * v[1] + v[2] * v[2], red);
    float inv = 1.f / fmaxf(sqrtf(ss), 1e-12f);
#pragma unroll
    for (int i = 0; i < 3; i++) v[i] *= inv;

    if (t == 0) {
        float* d1 = xfuse + (size_t)b * 1536 + 768;
        float* d2 = xfuse + (size_t)(BATCH + b) * 1536 + 768;
#pragma unroll
        for (int i = 0; i < 3; i++) {
            d1[tid + 256 * i] = v[i];
            d2[tid + 256 * i] = v[i];
        }
    } else {
        float* d1 = (t == 1) ? (xfuse + (size_t)b * 1536) : (xfuse + (size_t)(BATCH + b) * 1536);
#pragma unroll
        for (int i = 0; i < 3; i++) d1[tid + 256 * i] = v[i];
    }

    float invl = 1.f / l;
    float* dst = attn_out + ((size_t)b * 3 + t) * SLEN;
#pragma unroll
    for (int i = 0; i < SLEN / 256; i++) {
        int s = tid + 256 * i;
        size_t idx = (size_t)b * SLEN + s;
        float L = logits[idx];
        float qv = (t == 0) ? (qm1[idx] + qm2[idx]) : ((t == 1) ? qm1[idx] : qm2[idx]);
        dst[s] = (qv > 0.f) ? expf(L) * invl : 0.f;
    }
}

// ---------------- launch ----------------
extern "C" void kernel_launch(void* const* d_in, const int* in_sizes, int n_in,
                              void* d_out, int out_size) {
    const int*   step     = (const int*)d_in[0];
    const float* ctx      = (const float*)d_in[1];
    const float* question = (const float*)d_in[2];
    const float* control  = (const float*)d_in[3];
    const float* qm1      = (const float*)d_in[4];
    const float* qm2      = (const float*)d_in[5];
    const float* W_pos    = (const float*)d_in[8];
    const float* b_pos    = (const float*)d_in[9];
    const float* ln1_g    = (const float*)d_in[10];
    const float* ln1_b    = (const float*)d_in[11];
    const float* W_cq     = (const float*)d_in[12];
    const float* b_cq     = (const float*)d_in[13];
    const float* ln2_g    = (const float*)d_in[14];
    const float* ln2_b    = (const float*)d_in[15];
    const float* W_attn   = (const float*)d_in[16];
    const float* b_attn   = (const float*)d_in[17];
    const float* W_fuse   = (const float*)d_in[18];
    const float* b_fuse   = (const float*)d_in[19];
    const float* ln3_g    = (const float*)d_in[20];
    const float* ln3_b    = (const float*)d_in[21];
    const float* ln4_g    = (const float*)d_in[22];
    const float* ln4_b    = (const float*)d_in[23];
    float* out = (float*)d_out;

    void* sp = nullptr;
    cudaGetSymbolAddress(&sp, g_scratch);
    float* s = (float*)sp;
    float* lin_pa   = s + OFF_LIN;
    float* lin_cq   = s + OFF_LIN + 24576;
    float* lin_fuse = s + OFF_LIN + 49152;

    const int mainSmem = 24712 * 4;  // ~98.8KB -> 2 CTAs/SM
    cudaFuncSetAttribute(k_main, cudaFuncAttributeMaxDynamicSharedMemorySize, mainSmem);

    k_zero<<<96, 256>>>(s + OFF_LIN, 24576);

    // pa = ln_relu(question @ W_pos[step] + b_pos[step])  (48 slices)
    k_gemm2<16, 8><<<dim3(3, 48, 4), NTHR>>>(question, 768, 768, nullptr, 0, W_pos, 768,
                                             lin_pa, step);
    k_reduce_ln<<<32, 768>>>(lin_pa, b_pos, step, s + OFF_PA,
                             ln1_g, ln1_b, nullptr, nullptr, nullptr, 0);
    // u = ln_relu([control|pa] @ W_cq + b_cq) * W_attn    (48 slices)
    k_gemm2<48, 8><<<dim3(3, 48, 4), NTHR>>>(control, 1536, 1536, s + OFF_PA, 768, W_cq, 2304,
                                             lin_cq, nullptr);
    k_reduce_ln<<<32, 768>>>(lin_cq, b_cq, nullptr, s + OFF_U,
                             ln2_g, ln2_b, nullptr, nullptr, W_attn, 0);
    // main context pass (512 CTAs, dbl-buffered, warp-owned softmax, 2 barriers/tile)
    k_main<<<dim3(BATCH, CHUNKS), NTHR, mainSmem>>>(ctx, qm1, qm2, b_attn, s + OFF_U,
                                                    s + OFF_LOGITS, s + OFF_LPART,
                                                    s + OFF_ACCPART);
    // combine + l2norm + xfuse + attention maps
    k_combine_attn<<<dim3(BATCH, 3), NTHR>>>(s + OFF_LPART, s + OFF_ACCPART, s + OFF_LOGITS,
                                             qm1, qm2, s + OFF_XFUSE, out + BATCH * 1536);
    // ctrl1/ctrl2 = ln_relu(xfuse @ W_fuse + b_fuse) -> out (48 slices)
    k_gemm2<32, 8><<<dim3(3, 48, 8), NTHR>>>(s + OFF_XFUSE, 1536, 1536, nullptr, 0, W_fuse,
                                             1536, lin_fuse, nullptr);
    k_reduce_ln<<<64, 768>>>(lin_fuse, b_fuse, nullptr, out,
                             ln3_g, ln3_b, ln4_g, ln4_b, nullptr, 1);
}